// round 6
// baseline (speedup 1.0000x reference)
#include <cuda_runtime.h>
#include <math_constants.h>

// Round 6: two-kernel split, k2 restructured for MLP.
//  k1: block-per-segment lse -> g_lse (reads 64MB, leaves logits in L2)
//  k2: flat write kernel; per thread: batch-load 8 float4 into regs (MLP=8),
//      THEN do segment mapping + subtract + streaming store.

#define T1 128
#define T2 256
#define IT2 8
#define CHUNK (T2 * IT2)          // 2048 float4 = 8192 elems per k2 block

__device__ float g_lse[1 << 16];

__device__ __forceinline__ float warp_sum(float v) {
    #pragma unroll
    for (int o = 16; o > 0; o >>= 1)
        v += __shfl_xor_sync(0xFFFFFFFFu, v, o);
    return v;
}

// ---------------- k1: per-segment lse ----------------
__global__ void __launch_bounds__(T1)
lse_kernel(const float* __restrict__ logits,
           const int* __restrict__ prefix_sum) {
    __shared__ float sm[T1 / 32];

    const int seg   = blockIdx.x;
    const int start = (seg == 0) ? 0 : __ldg(&prefix_sum[seg - 1]);
    const int end   = __ldg(&prefix_sum[seg]);
    if (start >= end) return;

    const int tid  = threadIdx.x;
    const int lane = tid & 31;
    const int warp = tid >> 5;

    int astart = (start + 3) & ~3; if (astart > end) astart = end;
    int aend   = end & ~3;         if (aend < astart) aend = astart;

    const float4* __restrict__ logits4 = (const float4*)logits;

    float s = 0.0f;
    for (int i = start + tid; i < astart; i += T1)
        s += __expf(__ldg(&logits[i]));

    // batched body: 4 loads in flight per step, then exps
    int i = astart + tid * 4;
    for (; i + 3 * T1 * 4 < aend; i += 4 * T1 * 4) {
        float4 v0 = __ldg(&logits4[(i              ) >> 2]);
        float4 v1 = __ldg(&logits4[(i +     T1 * 4) >> 2]);
        float4 v2 = __ldg(&logits4[(i + 2 * T1 * 4) >> 2]);
        float4 v3 = __ldg(&logits4[(i + 3 * T1 * 4) >> 2]);
        s += __expf(v0.x) + __expf(v0.y) + __expf(v0.z) + __expf(v0.w);
        s += __expf(v1.x) + __expf(v1.y) + __expf(v1.z) + __expf(v1.w);
        s += __expf(v2.x) + __expf(v2.y) + __expf(v2.z) + __expf(v2.w);
        s += __expf(v3.x) + __expf(v3.y) + __expf(v3.z) + __expf(v3.w);
    }
    for (; i < aend; i += T1 * 4) {
        float4 v = __ldg(&logits4[i >> 2]);
        s += __expf(v.x) + __expf(v.y) + __expf(v.z) + __expf(v.w);
    }

    for (int j = aend + tid; j < end; j += T1)
        s += __expf(__ldg(&logits[j]));

    s = warp_sum(s);
    if (lane == 0) sm[warp] = s;
    __syncthreads();
    if (warp == 0) {
        float v = (lane < T1 / 32) ? sm[lane] : 0.0f;
        #pragma unroll
        for (int o = (T1 / 32) / 2; o > 0; o >>= 1)
            v += __shfl_xor_sync(0xFFFFFFFFu, v, o);
        if (lane == 0) g_lse[seg] = __logf(v);
    }
}

// ---------------- k2: flat write, load-batched ----------------
__global__ void __launch_bounds__(T2)
write_kernel(const float* __restrict__ logits,
             const int* __restrict__ prefix_sum,
             float* __restrict__ out,
             int total4, int nseg) {
    const int tid   = threadIdx.x;
    const int base4 = blockIdx.x * CHUNK;

    if (base4 + tid >= total4) return;

    const float4* __restrict__ logits4 = (const float4*)logits;
    float4*       __restrict__ out4    = (float4*)out;

    // ---- Phase A: batch all loads (MLP = IT2) ----
    float4 v[IT2];
    int nit = 0;
    #pragma unroll
    for (int it = 0; it < IT2; it++) {
        int i4 = base4 + tid + it * T2;
        if (i4 < total4) { v[it] = __ldg(&logits4[i4]); nit = it + 1; }
    }

    // ---- Phase B: segment mapping + store ----
    // binary search: seg = first j with prefix_sum[j] > first element index
    int e0 = (base4 + tid) * 4;
    int lo = 0, hi = nseg;
    while (lo < hi) {
        int mid = (lo + hi) >> 1;
        if (__ldg(&prefix_sum[mid]) <= e0) lo = mid + 1; else hi = mid;
    }
    int seg = lo;
    int pe  = __ldg(&prefix_sum[seg]);
    float L = g_lse[seg];

    #pragma unroll
    for (int it = 0; it < IT2; it++) {
        if (it >= nit) break;
        int e = (base4 + tid + it * T2) * 4;

        if (e >= pe) {                     // advance (rare: ~3% of iters)
            do { pe = __ldg(&prefix_sum[++seg]); } while (e >= pe);
            L = g_lse[seg];
        }

        float4 r;
        if (e + 4 <= pe) {                 // common: whole float4 in one segment
            r.x = v[it].x - L; r.y = v[it].y - L;
            r.z = v[it].z - L; r.w = v[it].w - L;
        } else {                           // boundary inside the float4
            int s2 = seg, p2 = pe;
            float xs[4] = {v[it].x, v[it].y, v[it].z, v[it].w};
            float rs[4];
            #pragma unroll
            for (int k = 0; k < 4; k++) {
                while (e + k >= p2) p2 = __ldg(&prefix_sum[++s2]);
                rs[k] = xs[k] - g_lse[s2];
            }
            r.x = rs[0]; r.y = rs[1]; r.z = rs[2]; r.w = rs[3];
        }
        __stcs(&out4[base4 + tid + it * T2], r);
    }
}

extern "C" void kernel_launch(void* const* d_in, const int* in_sizes, int n_in,
                              void* d_out, int out_size) {
    const float* logits     = (const float*)d_in[0];
    const int*   prefix_sum = (const int*)d_in[1];
    float*       out        = (float*)d_out;

    const int num_segs = in_sizes[1];
    const int total4   = out_size >> 2;          // total multiple of 4
    const int grid2    = (total4 + CHUNK - 1) / CHUNK;

    lse_kernel<<<num_segs, T1>>>(logits, prefix_sum);
    write_kernel<<<grid2, T2>>>(logits, prefix_sum, out, total4, num_segs);
}

// round 7
// speedup vs baseline: 1.0444x; 1.0444x over previous
#include <cuda_runtime.h>
#include <math_constants.h>

// Round 7: two-kernel split; k2 uses a block-local SMEM segment table so the
// element->segment mapping has NO serial global-memory chain.
//  k1: block-per-segment lse -> g_lse (reads 64MB at ~6TB/s)
//  k2: flat write; block covers 8192 elems, smem table of segment ends+lse.

#define T1 128
#define T2 256
#define IT2 8
#define CHUNK4 (T2 * IT2)          // 2048 float4 = 8192 elems per k2 block
#define TBL 160                    // smem segment-table entries (>> max/block)

__device__ float g_lse[1 << 16];

__device__ __forceinline__ float warp_sum(float v) {
    #pragma unroll
    for (int o = 16; o > 0; o >>= 1)
        v += __shfl_xor_sync(0xFFFFFFFFu, v, o);
    return v;
}

// ---------------- k1: per-segment lse ----------------
__global__ void __launch_bounds__(T1)
lse_kernel(const float* __restrict__ logits,
           const int* __restrict__ prefix_sum) {
    __shared__ float sm[T1 / 32];

    const int seg   = blockIdx.x;
    const int start = (seg == 0) ? 0 : __ldg(&prefix_sum[seg - 1]);
    const int end   = __ldg(&prefix_sum[seg]);
    if (start >= end) return;

    const int tid  = threadIdx.x;
    const int lane = tid & 31;
    const int warp = tid >> 5;

    int astart = (start + 3) & ~3; if (astart > end) astart = end;
    int aend   = end & ~3;         if (aend < astart) aend = astart;

    const float4* __restrict__ logits4 = (const float4*)logits;

    float s = 0.0f;
    for (int i = start + tid; i < astart; i += T1)
        s += __expf(__ldg(&logits[i]));

    int i = astart + tid * 4;
    for (; i + 3 * T1 * 4 < aend; i += 4 * T1 * 4) {
        float4 v0 = __ldg(&logits4[(i              ) >> 2]);
        float4 v1 = __ldg(&logits4[(i +     T1 * 4) >> 2]);
        float4 v2 = __ldg(&logits4[(i + 2 * T1 * 4) >> 2]);
        float4 v3 = __ldg(&logits4[(i + 3 * T1 * 4) >> 2]);
        s += __expf(v0.x) + __expf(v0.y) + __expf(v0.z) + __expf(v0.w);
        s += __expf(v1.x) + __expf(v1.y) + __expf(v1.z) + __expf(v1.w);
        s += __expf(v2.x) + __expf(v2.y) + __expf(v2.z) + __expf(v2.w);
        s += __expf(v3.x) + __expf(v3.y) + __expf(v3.z) + __expf(v3.w);
    }
    for (; i < aend; i += T1 * 4) {
        float4 v = __ldg(&logits4[i >> 2]);
        s += __expf(v.x) + __expf(v.y) + __expf(v.z) + __expf(v.w);
    }
    for (int j = aend + tid; j < end; j += T1)
        s += __expf(__ldg(&logits[j]));

    s = warp_sum(s);
    if (lane == 0) sm[warp] = s;
    __syncthreads();
    if (warp == 0) {
        float v = (lane < T1 / 32) ? sm[lane] : 0.0f;
        #pragma unroll
        for (int o = (T1 / 32) / 2; o > 0; o >>= 1)
            v += __shfl_xor_sync(0xFFFFFFFFu, v, o);
        if (lane == 0) g_lse[seg] = __logf(v);
    }
}

// global fallback (effectively never taken): seg of element e
__device__ __forceinline__ float lse_global(const int* __restrict__ prefix_sum,
                                            int nseg, int e) {
    int lo = 0, hi = nseg;
    while (lo < hi) {
        int mid = (lo + hi) >> 1;
        if (__ldg(&prefix_sum[mid]) <= e) lo = mid + 1; else hi = mid;
    }
    return g_lse[lo];
}

// ---------------- k2: flat write with smem segment table ----------------
__global__ void __launch_bounds__(T2)
write_kernel(const float* __restrict__ logits,
             const int* __restrict__ prefix_sum,
             float* __restrict__ out,
             int total4, int nseg) {
    __shared__ int   s_end[TBL];
    __shared__ float s_lse[TBL];
    __shared__ int   s_s0;

    const int tid   = threadIdx.x;
    const int base4 = blockIdx.x * CHUNK4;
    const int base  = base4 * 4;

    // one thread: binary search for first segment owning `base`
    if (tid == 0) {
        int lo = 0, hi = nseg;
        while (lo < hi) {
            int mid = (lo + hi) >> 1;
            if (__ldg(&prefix_sum[mid]) <= base) lo = mid + 1; else hi = mid;
        }
        s_s0 = lo;
    }
    __syncthreads();
    const int s0 = s_s0;

    // cooperative table fill (ends monotone; pad with INT_MAX past nseg)
    for (int k = tid; k < TBL; k += T2) {
        int sj = s0 + k;
        if (sj < nseg) {
            s_end[k] = __ldg(&prefix_sum[sj]);
            s_lse[k] = g_lse[sj];
        } else {
            s_end[k] = 0x7FFFFFFF;
            s_lse[k] = 0.0f;
        }
    }
    __syncthreads();

    const float4* __restrict__ logits4 = (const float4*)logits;
    float4*       __restrict__ out4    = (float4*)out;

    int k = 0;  // monotone smem table cursor (per thread)

    #pragma unroll
    for (int it = 0; it < IT2; it++) {
        int i4 = base4 + tid + it * T2;
        if (i4 >= total4) break;
        int e = i4 * 4;

        float4 v = __ldg(&logits4[i4]);

        while (e >= s_end[k] && k < TBL - 1) k++;   // smem walk, independent/thread

        float4 r;
        int ke = s_end[k];
        if (e >= ke) {                               // table overflow fallback
            r.x = v.x - lse_global(prefix_sum, nseg, e);
            r.y = v.y - lse_global(prefix_sum, nseg, e + 1);
            r.z = v.z - lse_global(prefix_sum, nseg, e + 2);
            r.w = v.w - lse_global(prefix_sum, nseg, e + 3);
        } else if (e + 4 <= ke) {                    // common: single segment
            float L = s_lse[k];
            r.x = v.x - L; r.y = v.y - L; r.z = v.z - L; r.w = v.w - L;
        } else {                                     // boundary inside float4
            int kk = k;
            float xs[4] = {v.x, v.y, v.z, v.w};
            float rs[4];
            #pragma unroll
            for (int q = 0; q < 4; q++) {
                while (e + q >= s_end[kk] && kk < TBL - 1) kk++;
                rs[q] = (e + q >= s_end[kk])
                          ? xs[q] - lse_global(prefix_sum, nseg, e + q)
                          : xs[q] - s_lse[kk];
            }
            r.x = rs[0]; r.y = rs[1]; r.z = rs[2]; r.w = rs[3];
        }
        __stcs(&out4[i4], r);
    }
}

extern "C" void kernel_launch(void* const* d_in, const int* in_sizes, int n_in,
                              void* d_out, int out_size) {
    const float* logits     = (const float*)d_in[0];
    const int*   prefix_sum = (const int*)d_in[1];
    float*       out        = (float*)d_out;

    const int num_segs = in_sizes[1];
    const int total4   = out_size >> 2;
    const int grid2    = (total4 + CHUNK4 - 1) / CHUNK4;

    lse_kernel<<<num_segs, T1>>>(logits, prefix_sum);
    write_kernel<<<grid2, T2>>>(logits, prefix_sum, out, total4, num_segs);
}